// round 13
// baseline (speedup 1.0000x reference)
#include <cuda_runtime.h>
#include <cuda_bf16.h>

// Problem constants (fixed by the dataset): B=32, L=256, V=50000, C=128
#define CC   128
#define LL   256
#define NB   4          // batches per CTA
#define BDIM (128 * NB) // 512 threads: thread = (batch g, state j)

typedef unsigned int u32;

__device__ __forceinline__ u32 bf2_fma(u32 a, u32 b, u32 c) {
    u32 d; asm("fma.rn.bf16x2 %0, %1, %2, %3;" : "=r"(d) : "r"(a), "r"(b), "r"(c)); return d;
}
__device__ __forceinline__ u32 bf2_add(u32 a, u32 b) {
    u32 d; asm("add.rn.bf16x2 %0, %1, %2;" : "=r"(d) : "r"(a), "r"(b)); return d;
}
__device__ __forceinline__ u32 bf2_pack(float lo, float hi) {
    // cvt.rn.bf16x2.f32 d, a, b -> d.hi = cvt(a), d.lo = cvt(b)
    u32 d; asm("cvt.rn.bf16x2.f32 %0, %1, %2;" : "=r"(d) : "f"(hi), "f"(lo)); return d;
}
__device__ __forceinline__ float bf2_lo(u32 v) { return __uint_as_float(v << 16); }
__device__ __forceinline__ float bf2_hi(u32 v) { return __uint_as_float(v & 0xFFFF0000u); }
__device__ __forceinline__ float frcp_ap(float x) {
    float r; asm("rcp.approx.f32 %0, %1;" : "=f"(r) : "f"(x)); return r;
}

__global__ __launch_bounds__(BDIM, 1)
void crf_fwd_kernel(const int*   __restrict__ tokens,
                    const int*   __restrict__ target,
                    const float* __restrict__ mask,
                    const float* __restrict__ st,      // state_table [V, C]
                    const float* __restrict__ trans,   // trans_matrix [C, C]
                    float*       __restrict__ out)     // [B]
{
    // Per batch-group g: p stored ONCE as bf16 pairs (word k = {p[2k], p[2k+1]}),
    // 64 words, double buffered. All 4 warps of a group read the same addresses
    // (pure broadcast). One shared __syncthreads per step serves all NB groups.
    __shared__ __align__(16) u32 p2_s[NB][2][64];
    __shared__ int   tok_s[NB][LL];
    __shared__ float m_s[NB][LL];
    __shared__ float red_s[NB * 4], red2_s[NB * 4];

    const int tid = threadIdx.x;
    const int g   = tid >> 7;          // batch group 0..NB-1
    const int j   = tid & 127;         // this thread owns state j of its group
    const int w   = tid >> 5;          // global warp id
    const int b   = blockIdx.x * NB + g;

    // ---- stage tokens/mask (LL = 2*128 per group) + target-energy partial ----
    float tgt_part = 0.0f;
#pragma unroll
    for (int t = j; t < LL; t += 128) {
        tok_s[g][t] = tokens[b * LL + t];
        m_s[g][t]   = mask[b * LL + t];
        const int tg   = target[b * LL + t];
        const int prev = (t == 0) ? (CC - 1) : target[b * LL + t - 1];
        tgt_part += (trans[prev * CC + tg] + st[tok_s[g][t] * CC + tg]) * m_s[g][t];
    }

    // ---- E2[k] = bf16x2{ exp(trans[2k][j]), exp(trans[2k+1][j]) }, k = 0..63 ----
    u32 E2[64];
#pragma unroll
    for (int k = 0; k < 64; ++k)
        E2[k] = bf2_pack(__expf(trans[(2 * k) * CC + j]),
                         __expf(trans[(2 * k + 1) * CC + j]));
    __syncthreads();   // tok_s/m_s visible

    // ---- init: p_1[j] = exp((trans[C-1][j] + em_0[j]) * m0) ----
    __nv_bfloat16* pb0 = reinterpret_cast<__nv_bfloat16*>(&p2_s[g][0][0]);
    __nv_bfloat16* pb1 = reinterpret_cast<__nv_bfloat16*>(&p2_s[g][1][0]);
    const float m0 = m_s[g][0];
    float p = __expf((trans[(CC - 1) * CC + j] + st[tok_s[g][0] * CC + j]) * m0);
    pb0[j] = __float2bfloat16(p);

    // emission pipeline, depth 3: ec = exp(em[t]), en = exp(em[t+1]), raw = em[t+2]
    float ec  = __expf(st[tok_s[g][1] * CC + j]);
    float en  = __expf(st[tok_s[g][2] * CC + j]);
    float raw = st[tok_s[g][3] * CC + j];

    float S = 0.0f;    // accumulated shift; true part[j] = log p[j] + S
    __syncthreads();

    // ---- sequential scan: in-thread full matvec, 0 shfl, 1 shared bar/step ----
    for (int t = 1; t < LL; ++t) {
        const int rb = (t - 1) & 1, wb = t & 1;

        const float p0  = bf2_lo(p2_s[g][rb][0]);  // stored-bf16 normalizer
        const float inv = frcp_ap(p0);             // overlaps the matvec
        const float mt  = m_s[g][t];

        // issue LDG for emission row t+3 (clamped) — consumed NEXT iteration
        const int tpre = (t + 3 < LL) ? (t + 3) : (LL - 1);
        const float emr = __ldg(&st[tok_s[g][tpre] * CC + j]);

        // s_j = sum_i p[i] * E[i][j]: 64 HFMA2 over i-pairs, 8 indep chains
        const uint4* ap = reinterpret_cast<const uint4*>(&p2_s[g][rb][0]);
        u32 a0 = 0, a1 = 0, a2 = 0, a3 = 0, a4 = 0, a5 = 0, a6 = 0, a7 = 0;
#pragma unroll
        for (int k = 0; k < 8; ++k) {
            const uint4 v0 = ap[2 * k];
            const uint4 v1 = ap[2 * k + 1];
            a0 = bf2_fma(v0.x, E2[8 * k + 0], a0);
            a1 = bf2_fma(v0.y, E2[8 * k + 1], a1);
            a2 = bf2_fma(v0.z, E2[8 * k + 2], a2);
            a3 = bf2_fma(v0.w, E2[8 * k + 3], a3);
            a4 = bf2_fma(v1.x, E2[8 * k + 4], a4);
            a5 = bf2_fma(v1.y, E2[8 * k + 5], a5);
            a6 = bf2_fma(v1.z, E2[8 * k + 6], a6);
            a7 = bf2_fma(v1.w, E2[8 * k + 7], a7);
        }
        // one bf16x2 add level (4 instrs), then fp32 tree; s = lo-sum + hi-sum
        const u32 c0 = bf2_add(a0, a1), c1 = bf2_add(a2, a3);
        const u32 c2 = bf2_add(a4, a5), c3 = bf2_add(a6, a7);
        const float s = ((bf2_lo(c0) + bf2_lo(c1)) + (bf2_lo(c2) + bf2_lo(c3)))
                      + ((bf2_hi(c0) + bf2_hi(c1)) + (bf2_hi(c2) + bf2_hi(c3)));

        // branchless masked update (reference blend formula)
        const float pn = s * ec * inv;
        p += (pn - p) * mt;
        if (j == 0) S += mt * __logf(p0);          // off-path, 1 thread per group

        // single bf16 scalar store (adjacent threads fill one u32 word)
        ((wb) ? pb1 : pb0)[j] = __float2bfloat16(p);

        // rotate emission pipeline: exp consumes raw loaded LAST iteration
        ec  = en;
        en  = __expf(raw);
        raw = emr;
        __syncthreads();
    }

    // ---- epilogue: loss = S + log(sum_j p[j]) - tgt_energy ----
    float c = p;                                   // each state counted once
#pragma unroll
    for (int o = 16; o; o >>= 1) c += __shfl_xor_sync(0xffffffffu, c, o);
    float tp = tgt_part;
#pragma unroll
    for (int o = 16; o; o >>= 1) tp += __shfl_xor_sync(0xffffffffu, tp, o);
    if ((tid & 31) == 0) { red_s[w] = c; red2_s[w] = tp; }
    __syncthreads();

    if (j == 0) {      // one thread per group finalizes its batch
        const int wg = g * 4;
        const float ss = (red_s[wg]  + red_s[wg + 1])  + (red_s[wg + 2]  + red_s[wg + 3]);
        const float ts = (red2_s[wg] + red2_s[wg + 1]) + (red2_s[wg + 2] + red2_s[wg + 3]);
        out[b] = S + logf(ss) - ts;
    }
}

extern "C" void kernel_launch(void* const* d_in, const int* in_sizes, int n_in,
                              void* d_out, int out_size)
{
    const int*   tokens = (const int*)  d_in[0];
    const int*   target = (const int*)  d_in[1];
    const float* mask   = (const float*)d_in[2];
    const float* st     = (const float*)d_in[3];
    const float* trans  = (const float*)d_in[4];
    float*       out    = (float*)d_out;

    const int B = in_sizes[0] / LL;   // 32
    crf_fwd_kernel<<<B / NB, BDIM>>>(tokens, target, mask, st, trans, out);
}

// round 14
// speedup vs baseline: 2.5355x; 2.5355x over previous
#include <cuda_runtime.h>
#include <cuda_bf16.h>

// Problem constants (fixed by the dataset): B=32, L=256, V=50000, C=128
#define CC   128
#define LL   256
#define BDIM 128

typedef unsigned int u32;
typedef unsigned short u16;

__device__ __forceinline__ u32 bf2_fma(u32 a, u32 b, u32 c) {
    u32 d; asm("fma.rn.bf16x2 %0, %1, %2, %3;" : "=r"(d) : "r"(a), "r"(b), "r"(c)); return d;
}
__device__ __forceinline__ u32 bf2_add(u32 a, u32 b) {
    u32 d; asm("add.rn.bf16x2 %0, %1, %2;" : "=r"(d) : "r"(a), "r"(b)); return d;
}
__device__ __forceinline__ u32 bf2_pack(float lo, float hi) {
    // cvt.rn.bf16x2.f32 d, a, b -> d.hi = cvt(a), d.lo = cvt(b)
    u32 d; asm("cvt.rn.bf16x2.f32 %0, %1, %2;" : "=r"(d) : "f"(hi), "f"(lo)); return d;
}
__device__ __forceinline__ float bf2_lo(u32 v) { return __uint_as_float(v << 16); }
__device__ __forceinline__ float bf2_hi(u32 v) { return __uint_as_float(v & 0xFFFF0000u); }
__device__ __forceinline__ float frcp_ap(float x) {
    float r; asm("rcp.approx.f32 %0, %1;" : "=f"(r) : "f"(x)); return r;
}
// fast fp32 -> bf16 bits (round-to-nearest, half rounds away): IADD+SHF, not F2FP
__device__ __forceinline__ u16 f2bf_bits(float x) {
    return (u16)((__float_as_uint(x) + 0x8000u) >> 16);
}

__global__ __launch_bounds__(BDIM, 1)
void crf_fwd_kernel(const int*   __restrict__ tokens,
                    const int*   __restrict__ target,
                    const float* __restrict__ mask,
                    const float* __restrict__ st,      // state_table [V, C]
                    const float* __restrict__ trans,   // trans_matrix [C, C]
                    float*       __restrict__ out)     // [B]
{
    // p stored ONCE as bf16 pairs: word k = {p[2k](lo), p[2k+1](hi)}, 64 words,
    // double buffered. All threads read the same addresses (pure broadcast).
    __shared__ __align__(16) u32 p2_s[2][64];
    __shared__ int   tok_s[LL];
    __shared__ float m_s[LL];
    __shared__ float red_s[4], red2_s[4];

    const int b   = blockIdx.x;
    const int tid = threadIdx.x;
    const int w   = tid >> 5;
    const int l   = tid & 31;
    const int j   = tid;              // this thread owns state j (0..127)

    // ---- stage tokens/mask (LL = 2*BDIM) + target-energy partial ----
    float tgt_part = 0.0f;
#pragma unroll
    for (int t = tid; t < LL; t += BDIM) {
        tok_s[t] = tokens[b * LL + t];
        m_s[t]   = mask[b * LL + t];
        const int tg   = target[b * LL + t];
        const int prev = (t == 0) ? (CC - 1) : target[b * LL + t - 1];
        tgt_part += (trans[prev * CC + tg] + st[tok_s[t] * CC + tg]) * m_s[t];
    }

    // ---- E2[k] = bf16x2{ exp(trans[2k][j]), exp(trans[2k+1][j]) }, k = 0..63 ----
    u32 E2[64];
#pragma unroll
    for (int k = 0; k < 64; ++k)
        E2[k] = bf2_pack(__expf(trans[(2 * k) * CC + j]),
                         __expf(trans[(2 * k + 1) * CC + j]));
    __syncthreads();   // tok_s/m_s visible

    // ---- init: p_1[j] = exp((trans[C-1][j] + em_0[j]) * m0) ----
    u16* pb0 = reinterpret_cast<u16*>(&p2_s[0][0]);
    u16* pb1 = reinterpret_cast<u16*>(&p2_s[1][0]);
    const float m0 = m_s[0];
    float p = __expf((trans[(CC - 1) * CC + j] + st[tok_s[0] * CC + j]) * m0);
    pb0[j] = f2bf_bits(p);

    // emission pipeline, depth 4:
    //   ec = exp(em[t]), en = exp(em[t+1]), raw = em[t+2], raw2 = em[t+3]
    float ec   = __expf(st[tok_s[1] * CC + j]);
    float en   = __expf(st[tok_s[2] * CC + j]);
    float raw  = st[tok_s[3] * CC + j];
    float raw2 = st[tok_s[4] * CC + j];

    float S = 0.0f;    // accumulated shift; true part[j] = log p[j] + S
    __syncthreads();

    // ---- sequential scan: in-thread full matvec, 0 shfl, 1 bar/step ----
    for (int t = 1; t < LL; ++t) {
        const int rb = (t - 1) & 1, wb = t & 1;

        const float p0  = bf2_lo(p2_s[rb][0]);   // stored-bf16 normalizer (broadcast)
        const float inv = frcp_ap(p0);           // overlaps the matvec
        const float mt  = m_s[t];

        // early tail precompute (ready during the matvec):
        //   p_new = s*A + Cc  ==  (1-mt)*p + mt*(s*ec*inv)   (reference blend)
        const float A  = ec * inv * mt;
        const float Cc = p * (1.0f - mt);

        // issue LDG for emission row t+4 (clamped) — consumed 2 iterations later
        const int tpre = (t + 4 < LL) ? (t + 4) : (LL - 1);
        const float emr = __ldg(&st[tok_s[tpre] * CC + j]);

        // s_j = sum_i p[i] * E[i][j]: 64 HFMA2 over i-pairs, 8 indep chains
        const uint4* ap = reinterpret_cast<const uint4*>(&p2_s[rb][0]);
        u32 a0 = 0, a1 = 0, a2 = 0, a3 = 0, a4 = 0, a5 = 0, a6 = 0, a7 = 0;
#pragma unroll
        for (int k = 0; k < 8; ++k) {
            const uint4 v0 = ap[2 * k];
            const uint4 v1 = ap[2 * k + 1];
            a0 = bf2_fma(v0.x, E2[8 * k + 0], a0);
            a1 = bf2_fma(v0.y, E2[8 * k + 1], a1);
            a2 = bf2_fma(v0.z, E2[8 * k + 2], a2);
            a3 = bf2_fma(v0.w, E2[8 * k + 3], a3);
            a4 = bf2_fma(v1.x, E2[8 * k + 4], a4);
            a5 = bf2_fma(v1.y, E2[8 * k + 5], a5);
            a6 = bf2_fma(v1.z, E2[8 * k + 6], a6);
            a7 = bf2_fma(v1.w, E2[8 * k + 7], a7);
        }
        // combine: two bf16x2 levels (6 instrs), then short fp32 tree
        const u32 c0 = bf2_add(a0, a1), c1 = bf2_add(a2, a3);
        const u32 c2 = bf2_add(a4, a5), c3 = bf2_add(a6, a7);
        const u32 d0 = bf2_add(c0, c1), d1 = bf2_add(c2, c3);
        const float s = (bf2_lo(d0) + bf2_hi(d0)) + (bf2_lo(d1) + bf2_hi(d1));

        // one-FMA tail, then fast bf16 store
        p = fmaf(s, A, Cc);
        if (j == 0) S += mt * __logf(p0);        // off-path, thread 0 only
        ((wb) ? pb1 : pb0)[j] = f2bf_bits(p);

        // rotate emission pipeline (exp consumes a row loaded 2 iters ago)
        ec   = en;
        en   = __expf(raw);
        raw  = raw2;
        raw2 = emr;
        __syncthreads();
    }

    // ---- epilogue: loss = S + log(sum_j p[j]) - tgt_energy ----
    float c = p;                                  // each state counted once
#pragma unroll
    for (int o = 16; o; o >>= 1) c += __shfl_xor_sync(0xffffffffu, c, o);
    float tp = tgt_part;
#pragma unroll
    for (int o = 16; o; o >>= 1) tp += __shfl_xor_sync(0xffffffffu, tp, o);
    if (l == 0) { red_s[w] = c; red2_s[w] = tp; }
    __syncthreads();

    if (tid == 0) {
        const float ss = (red_s[0] + red_s[1]) + (red_s[2] + red_s[3]);
        const float ts = (red2_s[0] + red2_s[1]) + (red2_s[2] + red2_s[3]);
        out[b] = S + logf(ss) - ts;
    }
}

extern "C" void kernel_launch(void* const* d_in, const int* in_sizes, int n_in,
                              void* d_out, int out_size)
{
    const int*   tokens = (const int*)  d_in[0];
    const int*   target = (const int*)  d_in[1];
    const float* mask   = (const float*)d_in[2];
    const float* st     = (const float*)d_in[3];
    const float* trans  = (const float*)d_in[4];
    float*       out    = (float*)d_out;

    const int B = in_sizes[0] / LL;   // 32
    crf_fwd_kernel<<<B, BDIM>>>(tokens, target, mask, st, trans, out);
}